// round 11
// baseline (speedup 1.0000x reference)
#include <cuda_runtime.h>
#include <math.h>

#define NTOK 32768
#define NH 8
#define HD 24
#define HDIM 28
#define NSEG 48
#define CHUNK 4096

typedef unsigned long long ull;

#define FMA_F32X2(d, a, b, c) \
    asm("fma.rn.f32x2 %0, %1, %2, %3;" : "=l"(d) : "l"(a), "l"(b), "l"(c))
#define PACK_F32X2(out, lo, hi) \
    asm("mov.b64 %0, {%1, %2};" : "=l"(out) : "r"(lo), "r"(hi))
#define UNPACK_F32X2(lo, hi, in) \
    asm("mov.b64 {%0, %1}, %2;" : "=r"(lo), "=r"(hi) : "l"(in))

// ---------- scratch ----------
static __device__ float g_qkv[(size_t)NTOK * 576];
static __device__ float g_qhat[(size_t)NH * NTOK * HDIM];
static __device__ float g_khat[(size_t)NH * NTOK * HDIM];
static __device__ ull   g_keys[(size_t)NSEG * NTOK];
static __device__ float g_o[(size_t)24 * NTOK * HD];
static __device__ float g_z[(size_t)24 * NTOK];

__device__ __forceinline__ unsigned ford(float f) {
    unsigned u = __float_as_uint(f);
    return (u & 0x80000000u) ? ~u : (u | 0x80000000u);
}

__device__ __forceinline__ void cswap(ull& a, ull& b, bool asc) {
    if ((a > b) == asc) { ull t = a; a = b; b = t; }
}

__device__ __forceinline__ void tail8(ull e[8], bool asc) {
    #pragma unroll
    for (int r = 0; r < 4; r++) cswap(e[r], e[r + 4], asc);
    #pragma unroll
    for (int r = 0; r < 8; r++) if (!(r & 2)) cswap(e[r], e[r | 2], asc);
    #pragma unroll
    for (int r = 0; r < 8; r += 2) cswap(e[r], e[r + 1], asc);
}

template <int K>
__device__ __forceinline__ void reg_tail(ull e[8], int g0) {
    #pragma unroll
    for (int j = (K > 8 ? 4 : K / 2); j > 0; j >>= 1) {
        #pragma unroll
        for (int r = 0; r < 8; r++) {
            if (!(r & j)) {
                bool asc = (((g0 + r) & K) == 0);
                cswap(e[r], e[r | j], asc);
            }
        }
    }
}

__device__ __forceinline__ void spass4(ull* s, int pbase, int j, bool asc) {
    int i = ((pbase & ~(j - 1)) << 1) | (pbase & (j - 1));
    ulonglong2 a0 = *(ulonglong2*)(s + i);
    ulonglong2 a1 = *(ulonglong2*)(s + i + 2);
    ulonglong2 b0 = *(ulonglong2*)(s + i + j);
    ulonglong2 b1 = *(ulonglong2*)(s + i + j + 2);
    cswap(a0.x, b0.x, asc); cswap(a0.y, b0.y, asc);
    cswap(a1.x, b1.x, asc); cswap(a1.y, b1.y, asc);
    *(ulonglong2*)(s + i) = a0;
    *(ulonglong2*)(s + i + 2) = a1;
    *(ulonglong2*)(s + i + j) = b0;
    *(ulonglong2*)(s + i + j + 2) = b1;
}

// ---------- LayerNorm1 + QKV GEMM ----------
__global__ void __launch_bounds__(576) k_ln_qkv(
    const float* __restrict__ x, const float* __restrict__ g1, const float* __restrict__ b1,
    const float* __restrict__ Wq, const float* __restrict__ Wk, const float* __restrict__ Wv) {
    __shared__ __align__(16) float xnt[24][68];
    int base = blockIdx.x * 64;
    int tid = threadIdx.x;
    if (tid < 64) {
        int row = base + tid;
        float xv[24];
        float mu = 0.f;
        #pragma unroll
        for (int i = 0; i < 24; i++) { xv[i] = x[(size_t)row * 24 + i]; mu += xv[i]; }
        mu *= (1.f / 24.f);
        float var = 0.f;
        #pragma unroll
        for (int i = 0; i < 24; i++) { float d = xv[i] - mu; var += d * d; }
        var *= (1.f / 24.f);
        float inv = rsqrtf(var + 1e-5f);
        #pragma unroll
        for (int i = 0; i < 24; i++) xnt[i][tid] = (xv[i] - mu) * inv * g1[i] + b1[i];
    }
    __syncthreads();
    int col = tid;
    const float* W;
    int cc;
    if (col < 192)      { W = Wq; cc = col; }
    else if (col < 384) { W = Wk; cc = col - 192; }
    else                { W = Wv; cc = col - 384; }
    float w[24];
    #pragma unroll
    for (int i = 0; i < 24; i++) w[i] = W[i * 192 + cc];
    #pragma unroll 2
    for (int r4 = 0; r4 < 16; r4++) {
        float a0 = 0.f, a1 = 0.f, a2 = 0.f, a3 = 0.f;
        #pragma unroll
        for (int i = 0; i < 24; i++) {
            float4 xr = *(const float4*)&xnt[i][r4 * 4];
            a0 = fmaf(xr.x, w[i], a0);
            a1 = fmaf(xr.y, w[i], a1);
            a2 = fmaf(xr.z, w[i], a2);
            a3 = fmaf(xr.w, w[i], a3);
        }
        size_t o = (size_t)(base + r4 * 4) * 576 + col;
        g_qkv[o] = a0;
        g_qkv[o + 576] = a1;
        g_qkv[o + 1152] = a2;
        g_qkv[o + 1728] = a3;
    }
}

// ---------- build q_hat/k_hat + keys ----------
__global__ void __launch_bounds__(256) k_build(const float* __restrict__ coords,
                                               const float* __restrict__ alphas,
                                               const float* __restrict__ Wrpe) {
    __shared__ float stage[8 * 929];
    __shared__ ull ksm[48 * 32];
    __shared__ float wsm[16], wsqm[16];
    int tid = threadIdx.x;
    int n0 = blockIdx.x * 32;
    if (tid < 16) {
        int h = tid >> 1, c = tid & 1;
        float s = 0.f;
        for (int i = 0; i < 24; i++)
            for (int j = 0; j < 8; j++)
                s += Wrpe[(h * 24 + i) * 16 + c * 8 + j];
        s *= (1.f / 192.f);
        wsm[tid] = s * s;
        wsqm[tid] = sqrtf(2.f * s * s);
    }
    __syncthreads();

    int h = tid & 7, nl = tid >> 3;
    int n = n0 + nl;
    float p0 = coords[n * 3 + 1], p1 = coords[n * 3 + 2];
    float sqn = wsm[h * 2] * p0 * p0 + wsm[h * 2 + 1] * p1 * p1;
    float qp0 = wsqm[h * 2] * p0, qp1 = wsqm[h * 2 + 1] * p1;
    float qh[HDIM], kh[HDIM];
    const float* qkv = &g_qkv[(size_t)n * 576];
    const float qscale = 0.2041241452319315f;
    #pragma unroll
    for (int i = 0; i < 24; i++) { qh[i] = qkv[h * 24 + i] * qscale; kh[i] = qkv[192 + h * 24 + i]; }
    qh[24] = qp0; qh[25] = qp1; qh[26] = -sqn; qh[27] = 1.f;
    kh[24] = qp0; kh[25] = qp1; kh[26] = 1.f;  kh[27] = -sqn;

    #pragma unroll
    for (int r = 0; r < 3; r++) {
        const float* a = &alphas[(r * 8 + h) * HDIM];
        float sq = 0.f, sk = 0.f;
        #pragma unroll
        for (int i = 0; i < HDIM; i++) { sq = fmaf(qh[i], a[i], sq); sk = fmaf(kh[i], a[i], sk); }
        ksm[(r * 8 + h) * 32 + nl] = ((ull)ford(sq) << 32) | (unsigned)n;
        ksm[(24 + r * 8 + h) * 32 + nl] = ((ull)ford(sk) << 32) | (unsigned)n;
    }

    #pragma unroll
    for (int i = 0; i < HDIM; i++) stage[h * 929 + nl * 29 + i] = qh[i];
    __syncthreads();
    for (int e = tid; e < 8 * 896; e += 256) {
        int hh = e / 896, rr = e - hh * 896;
        g_qhat[(size_t)hh * NTOK * 28 + (size_t)n0 * 28 + rr] =
            stage[hh * 929 + (rr / 28) * 29 + rr % 28];
    }
    __syncthreads();
    #pragma unroll
    for (int i = 0; i < HDIM; i++) stage[h * 929 + nl * 29 + i] = kh[i];
    __syncthreads();
    for (int e = tid; e < 8 * 896; e += 256) {
        int hh = e / 896, rr = e - hh * 896;
        g_khat[(size_t)hh * NTOK * 28 + (size_t)n0 * 28 + rr] =
            stage[hh * 929 + (rr / 28) * 29 + rr % 28];
    }
    for (int e = tid; e < 48 * 32; e += 256) {
        int seg = e >> 5, nn = e & 31;
        g_keys[(size_t)seg * NTOK + n0 + nn] = ksm[e];
    }
}

// ---------- bitonic: presort ----------
__global__ void __launch_bounds__(512) k_presort() {
    __shared__ __align__(16) ull s[CHUNK];
    int seg = blockIdx.x >> 3, chunk = blockIdx.x & 7;
    size_t gb = (size_t)seg * NTOK + (size_t)chunk * CHUNK;
    int base = chunk * CHUNK;
    int t = threadIdx.x;
    int e0 = t * 8;
    int g0 = base + e0;

    ull e[8];
    #pragma unroll
    for (int r = 0; r < 8; r++) e[r] = g_keys[gb + e0 + r];
    reg_tail<2>(e, g0);
    reg_tail<4>(e, g0);
    reg_tail<8>(e, g0);
    #pragma unroll
    for (int r = 0; r < 8; r++) s[e0 + r] = e[r];
    __syncthreads();

    for (int k = 16; k <= CHUNK; k <<= 1) {
        for (int j = k >> 1; j >= 8; j >>= 1) {
            int pbase = t * 4;
            int i = ((pbase & ~(j - 1)) << 1) | (pbase & (j - 1));
            bool asc = (((base + i) & k) == 0);
            spass4(s, pbase, j, asc);
            __syncthreads();
        }
        #pragma unroll
        for (int r = 0; r < 8; r++) e[r] = s[e0 + r];
        bool asc = ((g0 & k) == 0);
        tail8(e, asc);
        if (k < CHUNK) {
            #pragma unroll
            for (int r = 0; r < 8; r++) s[e0 + r] = e[r];
            __syncthreads();
        }
    }
    #pragma unroll
    for (int r = 0; r < 8; r++) g_keys[gb + e0 + r] = e[r];
}

// ---------- fused global merge ----------
__global__ void __launch_bounds__(256) k_gmerge(int k) {
    int t = blockIdx.x * 256 + threadIdx.x;
    int seg = t >> 12;
    int g = t & 4095;
    size_t bs = (size_t)seg * NTOK;
    ull e[8];
    #pragma unroll
    for (int m = 0; m < 8; m++) e[m] = g_keys[bs + g + 4096 * m];
    #pragma unroll
    for (int j = 4; j >= 1; j >>= 1) {
        if (j * 8192 <= k) {
            #pragma unroll
            for (int m = 0; m < 8; m++) {
                if (!(m & j)) {
                    bool asc = (((m * 4096) & k) == 0);
                    cswap(e[m], e[m + j], asc);
                }
            }
        }
    }
    #pragma unroll
    for (int m = 0; m < 8; m++) g_keys[bs + g + 4096 * m] = e[m];
}

// ---------- bitonic: finish ----------
__global__ void __launch_bounds__(512) k_finish(int k) {
    __shared__ __align__(16) ull s[CHUNK];
    int seg = blockIdx.x >> 3, chunk = blockIdx.x & 7;
    size_t gb = (size_t)seg * NTOK + (size_t)chunk * CHUNK;
    int base = chunk * CHUNK;
    int t = threadIdx.x;
    int e0 = t * 8;
    #pragma unroll
    for (int u = 0; u < 2; u++) {
        int i = (t + u * 512) * 4;
        *(ulonglong2*)(s + i)     = *(const ulonglong2*)(g_keys + gb + i);
        *(ulonglong2*)(s + i + 2) = *(const ulonglong2*)(g_keys + gb + i + 2);
    }
    __syncthreads();
    bool asc = ((base & k) == 0);
    for (int j = CHUNK >> 1; j >= 8; j >>= 1) {
        spass4(s, t * 4, j, asc);
        __syncthreads();
    }
    ull e[8];
    #pragma unroll
    for (int r = 0; r < 8; r++) e[r] = s[e0 + r];
    tail8(e, asc);
    #pragma unroll
    for (int r = 0; r < 8; r++) g_keys[gb + e0 + r] = e[r];
}

// ---------- block attention v4b: LDS.128 everywhere, 256 threads (fixed layout) ----------
__global__ void __launch_bounds__(256) k_attn() {
    __shared__ __align__(16) float SP[10976];   // 43904 B
    float* qs_t = SP;                           // [kk][row] 28 x 132 : 0..3696
    float* ks_t = SP + 3696;                    // [kk][col] 28 x 132 : 3696..7392
    float* vs   = SP + 7392;                    // [col][d]  128 x 26 : 7392..10720
    int* qidx = (int*)(SP + 10720);             // 10720..10848
    int* kidx = (int*)(SP + 10848);             // 10848..10976
    float* pbuf = SP;                           // PV: [32 local cols][132] : 0..4224
    ull*  rbuf = (ull*)(SP + 4224);             // PV reduce: 128 x 12 ull : 4224..7296

    int tid = threadIdx.x;
    int b = blockIdx.x, h = blockIdx.y, r = blockIdx.z;
    int seg = r * 8 + h;

    if (tid < 128)
        qidx[tid] = (int)(g_keys[(size_t)seg * NTOK + b * 128 + tid] & 0xffffffffu);
    else {
        int t = tid - 128;
        kidx[t] = (int)(g_keys[(size_t)(24 + seg) * NTOK + b * 128 + t] & 0xffffffffu);
    }
    __syncthreads();
    for (int i = tid; i < 128 * 28; i += 256) {
        int row = i / 28, kk = i - row * 28;
        qs_t[kk * 132 + row] = g_qhat[((size_t)h * NTOK + qidx[row]) * HDIM + kk];
        ks_t[kk * 132 + row] = g_khat[((size_t)h * NTOK + kidx[row]) * HDIM + kk];
    }
    for (int i = tid; i < 128 * 24; i += 256) {
        int row = i / 24, kk = i - row * 24;
        vs[row * 26 + kk] = g_qkv[(size_t)kidx[row] * 576 + 384 + h * 24 + kk];
    }
    __syncthreads();

    int ty = tid >> 4, tx = tid & 15;
    int R0 = ty * 8;
    // acc2[u][c]: rows (R0+2u, R0+2u+1) packed; col gc = (c<4) ? 4tx+c : 64+4tx+(c-4)
    ull acc2[4][8];
    #pragma unroll
    for (int u = 0; u < 4; u++)
        #pragma unroll
        for (int c = 0; c < 8; c++) acc2[u][c] = 0ULL;

    #pragma unroll 2
    for (int kk = 0; kk < 28; kk++) {
        ulonglong2 q01 = *(const ulonglong2*)&qs_t[kk * 132 + R0];
        ulonglong2 q23 = *(const ulonglong2*)&qs_t[kk * 132 + R0 + 4];
        float4 ka = *(const float4*)&ks_t[kk * 132 + 4 * tx];
        float4 kb = *(const float4*)&ks_t[kk * 132 + 64 + 4 * tx];
        float kvals[8] = {ka.x, ka.y, ka.z, ka.w, kb.x, kb.y, kb.z, kb.w};
        ull qp[4] = {q01.x, q01.y, q23.x, q23.y};
        #pragma unroll
        for (int c = 0; c < 8; c++) {
            unsigned kbits = __float_as_uint(kvals[c]);
            ull kp;
            PACK_F32X2(kp, kbits, kbits);
            #pragma unroll
            for (int u = 0; u < 4; u++)
                FMA_F32X2(acc2[u][c], qp[u], kp, acc2[u][c]);
        }
    }

    // softmax per rowpair (transient unpack)
    #pragma unroll
    for (int u = 0; u < 4; u++) {
        float vlo[8], vhi[8];
        #pragma unroll
        for (int c = 0; c < 8; c++) {
            unsigned lo, hi;
            UNPACK_F32X2(lo, hi, acc2[u][c]);
            vlo[c] = __uint_as_float(lo);
            vhi[c] = __uint_as_float(hi);
        }
        float mlo = vlo[0], mhi = vhi[0];
        #pragma unroll
        for (int c = 1; c < 8; c++) { mlo = fmaxf(mlo, vlo[c]); mhi = fmaxf(mhi, vhi[c]); }
        #pragma unroll
        for (int s = 1; s < 16; s <<= 1) {
            mlo = fmaxf(mlo, __shfl_xor_sync(0xffffffffu, mlo, s));
            mhi = fmaxf(mhi, __shfl_xor_sync(0xffffffffu, mhi, s));
        }
        float slo = 0.f, shi = 0.f;
        #pragma unroll
        for (int c = 0; c < 8; c++) {
            vlo[c] = __expf(vlo[c] - mlo); slo += vlo[c];
            vhi[c] = __expf(vhi[c] - mhi); shi += vhi[c];
        }
        #pragma unroll
        for (int s = 1; s < 16; s <<= 1) {
            slo += __shfl_xor_sync(0xffffffffu, slo, s);
            shi += __shfl_xor_sync(0xffffffffu, shi, s);
        }
        float ilo = 1.f / slo, ihi = 1.f / shi;
        #pragma unroll
        for (int c = 0; c < 8; c++) {
            unsigned lo = __float_as_uint(vlo[c] * ilo);
            unsigned hi = __float_as_uint(vhi[c] * ihi);
            PACK_F32X2(acc2[u][c], lo, hi);
        }
        if (tx == 0) {
            g_z[(size_t)seg * NTOK + qidx[R0 + 2 * u]]     = __logf(slo) + mlo;
            g_z[(size_t)seg * NTOK + qidx[R0 + 2 * u + 1]] = __logf(shi) + mhi;
        }
    }

    // PV: 4 rounds of 32 cols; thread = (rowquad rq, dimgroup dgp of 6, col parity cp)
    int rq = tid & 31, dgp = (tid >> 5) & 3, cp = tid >> 7;
    ull oap[2][6];
    #pragma unroll
    for (int u = 0; u < 2; u++)
        #pragma unroll
        for (int d = 0; d < 6; d++) oap[u][d] = 0ULL;

    for (int rd = 0; rd < 4; rd++) {
        __syncthreads();
        if (rd < 2) {
            if ((tx >> 3) == rd) {
                #pragma unroll
                for (int c = 0; c < 4; c++) {
                    int lc = 4 * tx + c - 32 * rd;
                    #pragma unroll
                    for (int u = 0; u < 4; u++)
                        *(ull*)&pbuf[lc * 132 + R0 + 2 * u] = acc2[u][c];
                }
            }
        } else {
            if ((tx >> 3) == rd - 2) {
                #pragma unroll
                for (int c = 4; c < 8; c++) {
                    int lc = 64 + 4 * tx + (c - 4) - 32 * rd;
                    #pragma unroll
                    for (int u = 0; u < 4; u++)
                        *(ull*)&pbuf[lc * 132 + R0 + 2 * u] = acc2[u][c];
                }
            }
        }
        __syncthreads();
        #pragma unroll 4
        for (int i = 0; i < 16; i++) {
            int lc = 2 * i + cp;
            ulonglong2 p4 = *(const ulonglong2*)&pbuf[lc * 132 + 4 * rq];
            int gc = 32 * rd + lc;
            const ull* vv = (const ull*)&vs[gc * 26 + dgp * 6];
            #pragma unroll
            for (int dd = 0; dd < 3; dd++) {
                unsigned va, vb;
                UNPACK_F32X2(va, vb, vv[dd]);
                ull s0, s1;
                PACK_F32X2(s0, va, va);
                PACK_F32X2(s1, vb, vb);
                FMA_F32X2(oap[0][2 * dd],     p4.x, s0, oap[0][2 * dd]);
                FMA_F32X2(oap[1][2 * dd],     p4.y, s0, oap[1][2 * dd]);
                FMA_F32X2(oap[0][2 * dd + 1], p4.x, s1, oap[0][2 * dd + 1]);
                FMA_F32X2(oap[1][2 * dd + 1], p4.y, s1, oap[1][2 * dd + 1]);
            }
        }
    }

    // reduce col-parity halves through rbuf
    __syncthreads();
    int grp = tid & 127;
    if (cp == 1) {
        #pragma unroll
        for (int u = 0; u < 2; u++)
            #pragma unroll
            for (int d = 0; d < 6; d++)
                rbuf[grp * 12 + u * 6 + d] = oap[u][d];
    }
    __syncthreads();
    if (cp == 0) {
        unsigned oneb = 0x3f800000u;
        ull one2;
        PACK_F32X2(one2, oneb, oneb);
        #pragma unroll
        for (int u = 0; u < 2; u++)
            #pragma unroll
            for (int d = 0; d < 6; d++)
                FMA_F32X2(oap[u][d], one2, rbuf[grp * 12 + u * 6 + d], oap[u][d]);
        #pragma unroll
        for (int u = 0; u < 2; u++) {
            int row0 = 4 * rq + 2 * u;
            int n0 = qidx[row0], n1 = qidx[row0 + 1];
            float* o0 = &g_o[((size_t)seg * NTOK + n0) * 24 + dgp * 6];
            float* o1 = &g_o[((size_t)seg * NTOK + n1) * 24 + dgp * 6];
            #pragma unroll
            for (int dd = 0; dd < 3; dd++) {
                unsigned a0, a1, b0, b1;
                UNPACK_F32X2(a0, a1, oap[u][2 * dd]);
                UNPACK_F32X2(b0, b1, oap[u][2 * dd + 1]);
                ull w0, w1;
                PACK_F32X2(w0, a0, b0);
                PACK_F32X2(w1, a1, b1);
                *(ull*)&o0[2 * dd] = w0;
                *(ull*)&o1[2 * dd] = w1;
            }
        }
    }
}

// ---------- combine ----------
__global__ void __launch_bounds__(512) k_combine(
    const float* __restrict__ x, const float* __restrict__ Wo, const float* __restrict__ bo,
    const float* __restrict__ g2, const float* __restrict__ b2v,
    const float* __restrict__ W1, const float* __restrict__ b1v,
    const float* __restrict__ W2, const float* __restrict__ b2f,
    float* __restrict__ out) {
    __shared__ float Wo_s[4608];
    __shared__ float outs[16][192];
    __shared__ float wsm[16][24];
    __shared__ float hsm[16][24];
    __shared__ float fsm[16][24];
    int warp = threadIdx.x >> 5, lane = threadIdx.x & 31;
    int row = blockIdx.x * 16 + warp;

    for (int i = threadIdx.x; i < 4608; i += 512) Wo_s[i] = Wo[i];
    __syncthreads();

    if (lane < 8) {
        int h = lane;
        float z0 = g_z[(size_t)h * NTOK + row];
        float z1 = g_z[(size_t)(8 + h) * NTOK + row];
        float z2 = g_z[(size_t)(16 + h) * NTOK + row];
        float m = fmaxf(z0, fmaxf(z1, z2));
        float e0 = __expf(z0 - m), e1 = __expf(z1 - m), e2 = __expf(z2 - m);
        float inv = 1.f / (e0 + e1 + e2);
        wsm[warp][h * 3 + 0] = e0 * inv;
        wsm[warp][h * 3 + 1] = e1 * inv;
        wsm[warp][h * 3 + 2] = e2 * inv;
    }
    __syncwarp();
    #pragma unroll
    for (int u = 0; u < 6; u++) {
        int j = lane * 6 + u;
        int h = j / 24, d = j - h * 24;
        float a = 0.f;
        #pragma unroll
        for (int r = 0; r < 3; r++)
            a = fmaf(wsm[warp][h * 3 + r], g_o[((size_t)(r * 8 + h) * NTOK + row) * 24 + d], a);
        outs[warp][j] = a;
    }
    __syncwarp();
    float xv = 0.f;
    if (lane < 24) {
        float a = bo[lane];
        #pragma unroll 4
        for (int j = 0; j < 192; j++) a = fmaf(outs[warp][j], Wo_s[j * 24 + lane], a);
        xv = x[(size_t)row * 24 + lane] + a;
    }
    float s = (lane < 24) ? xv : 0.f;
    #pragma unroll
    for (int t = 16; t > 0; t >>= 1) s += __shfl_xor_sync(0xffffffffu, s, t);
    float mu = s * (1.f / 24.f);
    float dv = (lane < 24) ? (xv - mu) : 0.f;
    float v2 = dv * dv;
    #pragma unroll
    for (int t = 16; t > 0; t >>= 1) v2 += __shfl_xor_sync(0xffffffffu, v2, t);
    float inv = rsqrtf(v2 * (1.f / 24.f) + 1e-5f);
    if (lane < 24) hsm[warp][lane] = dv * inv * g2[lane] + b2v[lane];
    __syncwarp();
    if (lane < 24) {
        float f = b1v[lane];
        #pragma unroll
        for (int j = 0; j < 24; j++) f = fmaf(hsm[warp][j], W1[j * 24 + lane], f);
        fsm[warp][lane] = fmaxf(f, 0.f);
    }
    __syncwarp();
    if (lane < 24) {
        float f = b2f[lane];
        #pragma unroll
        for (int j = 0; j < 24; j++) f = fmaf(fsm[warp][j], W2[j * 24 + lane], f);
        out[(size_t)row * 24 + lane] = xv + f;
    }
}

extern "C" void kernel_launch(void* const* d_in, const int* in_sizes, int n_in,
                              void* d_out, int out_size) {
    const float* x      = (const float*)d_in[0];
    const float* coords = (const float*)d_in[1];
    const float* n1g    = (const float*)d_in[2];
    const float* n1b    = (const float*)d_in[3];
    const float* Wq     = (const float*)d_in[4];
    const float* Wk     = (const float*)d_in[5];
    const float* Wv     = (const float*)d_in[6];
    const float* wrpe   = (const float*)d_in[7];
    const float* Wo     = (const float*)d_in[8];
    const float* bo     = (const float*)d_in[9];
    const float* n2g    = (const float*)d_in[10];
    const float* n2b    = (const float*)d_in[11];
    const float* W1     = (const float*)d_in[12];
    const float* b1     = (const float*)d_in[13];
    const float* W2     = (const float*)d_in[14];
    const float* b2     = (const float*)d_in[15];
    const float* alphas = (const float*)d_in[16];
    float* out = (float*)d_out;

    k_ln_qkv<<<NTOK / 64, 576>>>(x, n1g, n1b, Wq, Wk, Wv);   // 1
    k_build<<<NTOK / 32, 256>>>(coords, alphas, wrpe);        // 2
    k_presort<<<NSEG * 8, 512>>>();                           // 3

    // probe at position 4 (ncu captures the 4th launch). Keys after presort
    // are a valid permutation; probe output is overwritten by real k_attn.
    {
        dim3 probe(32, NH, 1);   // 256 CTAs ≈ one wave
        k_attn<<<probe, 256>>>();                             // 4 (profiled)
    }

    k_gmerge<<<768, 256>>>(8192);                             // 5
    k_finish<<<NSEG * 8, 512>>>(8192);                        // 6
    k_gmerge<<<768, 256>>>(16384);                            // 7
    k_finish<<<NSEG * 8, 512>>>(16384);                       // 8
    k_gmerge<<<768, 256>>>(32768);                            // 9
    k_finish<<<NSEG * 8, 512>>>(32768);                       // 10

    dim3 ag(NTOK / 128, NH, 3);
    k_attn<<<ag, 256>>>();                                    // 11 (real)
    k_combine<<<NTOK / 16, 512>>>(x, Wo, bo, n2g, n2b, W1, b1, W2, b2, out);  // 12
}

// round 12
// speedup vs baseline: 1.1005x; 1.1005x over previous
#include <cuda_runtime.h>
#include <math.h>

#define NTOK 32768
#define NH 8
#define HD 24
#define HDIM 28
#define NSEG 48
#define CHUNK 4096

typedef unsigned long long ull;

#define FMA_F32X2(d, a, b, c) \
    asm("fma.rn.f32x2 %0, %1, %2, %3;" : "=l"(d) : "l"(a), "l"(b), "l"(c))
#define PACK_F32X2(out, lo, hi) \
    asm("mov.b64 %0, {%1, %2};" : "=l"(out) : "r"(lo), "r"(hi))
#define UNPACK_F32X2(lo, hi, in) \
    asm("mov.b64 {%0, %1}, %2;" : "=r"(lo), "=r"(hi) : "l"(in))

// ---------- scratch ----------
static __device__ float g_qkv[(size_t)NTOK * 576];
static __device__ float g_qhat[(size_t)NH * NTOK * HDIM];
static __device__ float g_khat[(size_t)NH * NTOK * HDIM];
static __device__ ull   g_keys[(size_t)NSEG * NTOK];
static __device__ float g_o[(size_t)24 * NTOK * HD];
static __device__ float g_z[(size_t)24 * NTOK];

__device__ __forceinline__ unsigned ford(float f) {
    unsigned u = __float_as_uint(f);
    return (u & 0x80000000u) ? ~u : (u | 0x80000000u);
}

__device__ __forceinline__ void cswap(ull& a, ull& b, bool asc) {
    if ((a > b) == asc) { ull t = a; a = b; b = t; }
}

__device__ __forceinline__ void tail8(ull e[8], bool asc) {
    #pragma unroll
    for (int r = 0; r < 4; r++) cswap(e[r], e[r + 4], asc);
    #pragma unroll
    for (int r = 0; r < 8; r++) if (!(r & 2)) cswap(e[r], e[r | 2], asc);
    #pragma unroll
    for (int r = 0; r < 8; r += 2) cswap(e[r], e[r + 1], asc);
}

template <int K>
__device__ __forceinline__ void reg_tail(ull e[8], int g0) {
    #pragma unroll
    for (int j = (K > 8 ? 4 : K / 2); j > 0; j >>= 1) {
        #pragma unroll
        for (int r = 0; r < 8; r++) {
            if (!(r & j)) {
                bool asc = (((g0 + r) & K) == 0);
                cswap(e[r], e[r | j], asc);
            }
        }
    }
}

__device__ __forceinline__ void spass4(ull* s, int pbase, int j, bool asc) {
    int i = ((pbase & ~(j - 1)) << 1) | (pbase & (j - 1));
    ulonglong2 a0 = *(ulonglong2*)(s + i);
    ulonglong2 a1 = *(ulonglong2*)(s + i + 2);
    ulonglong2 b0 = *(ulonglong2*)(s + i + j);
    ulonglong2 b1 = *(ulonglong2*)(s + i + j + 2);
    cswap(a0.x, b0.x, asc); cswap(a0.y, b0.y, asc);
    cswap(a1.x, b1.x, asc); cswap(a1.y, b1.y, asc);
    *(ulonglong2*)(s + i) = a0;
    *(ulonglong2*)(s + i + 2) = a1;
    *(ulonglong2*)(s + i + j) = b0;
    *(ulonglong2*)(s + i + j + 2) = b1;
}

// ---------- LayerNorm1 + QKV GEMM ----------
__global__ void __launch_bounds__(576) k_ln_qkv(
    const float* __restrict__ x, const float* __restrict__ g1, const float* __restrict__ b1,
    const float* __restrict__ Wq, const float* __restrict__ Wk, const float* __restrict__ Wv) {
    __shared__ __align__(16) float xnt[24][68];
    int base = blockIdx.x * 64;
    int tid = threadIdx.x;
    if (tid < 64) {
        int row = base + tid;
        float xv[24];
        float mu = 0.f;
        #pragma unroll
        for (int i = 0; i < 24; i++) { xv[i] = x[(size_t)row * 24 + i]; mu += xv[i]; }
        mu *= (1.f / 24.f);
        float var = 0.f;
        #pragma unroll
        for (int i = 0; i < 24; i++) { float d = xv[i] - mu; var += d * d; }
        var *= (1.f / 24.f);
        float inv = rsqrtf(var + 1e-5f);
        #pragma unroll
        for (int i = 0; i < 24; i++) xnt[i][tid] = (xv[i] - mu) * inv * g1[i] + b1[i];
    }
    __syncthreads();
    int col = tid;
    const float* W;
    int cc;
    if (col < 192)      { W = Wq; cc = col; }
    else if (col < 384) { W = Wk; cc = col - 192; }
    else                { W = Wv; cc = col - 384; }
    float w[24];
    #pragma unroll
    for (int i = 0; i < 24; i++) w[i] = W[i * 192 + cc];
    #pragma unroll 2
    for (int r4 = 0; r4 < 16; r4++) {
        float a0 = 0.f, a1 = 0.f, a2 = 0.f, a3 = 0.f;
        #pragma unroll
        for (int i = 0; i < 24; i++) {
            float4 xr = *(const float4*)&xnt[i][r4 * 4];
            a0 = fmaf(xr.x, w[i], a0);
            a1 = fmaf(xr.y, w[i], a1);
            a2 = fmaf(xr.z, w[i], a2);
            a3 = fmaf(xr.w, w[i], a3);
        }
        size_t o = (size_t)(base + r4 * 4) * 576 + col;
        g_qkv[o] = a0;
        g_qkv[o + 576] = a1;
        g_qkv[o + 1152] = a2;
        g_qkv[o + 1728] = a3;
    }
}

// ---------- build q_hat/k_hat + keys ----------
__global__ void __launch_bounds__(256) k_build(const float* __restrict__ coords,
                                               const float* __restrict__ alphas,
                                               const float* __restrict__ Wrpe) {
    __shared__ float stage[8 * 929];
    __shared__ ull ksm[48 * 32];
    __shared__ float wsm[16], wsqm[16];
    int tid = threadIdx.x;
    int n0 = blockIdx.x * 32;
    if (tid < 16) {
        int h = tid >> 1, c = tid & 1;
        float s = 0.f;
        for (int i = 0; i < 24; i++)
            for (int j = 0; j < 8; j++)
                s += Wrpe[(h * 24 + i) * 16 + c * 8 + j];
        s *= (1.f / 192.f);
        wsm[tid] = s * s;
        wsqm[tid] = sqrtf(2.f * s * s);
    }
    __syncthreads();

    int h = tid & 7, nl = tid >> 3;
    int n = n0 + nl;
    float p0 = coords[n * 3 + 1], p1 = coords[n * 3 + 2];
    float sqn = wsm[h * 2] * p0 * p0 + wsm[h * 2 + 1] * p1 * p1;
    float qp0 = wsqm[h * 2] * p0, qp1 = wsqm[h * 2 + 1] * p1;
    float qh[HDIM], kh[HDIM];
    const float* qkv = &g_qkv[(size_t)n * 576];
    const float qscale = 0.2041241452319315f;
    #pragma unroll
    for (int i = 0; i < 24; i++) { qh[i] = qkv[h * 24 + i] * qscale; kh[i] = qkv[192 + h * 24 + i]; }
    qh[24] = qp0; qh[25] = qp1; qh[26] = -sqn; qh[27] = 1.f;
    kh[24] = qp0; kh[25] = qp1; kh[26] = 1.f;  kh[27] = -sqn;

    #pragma unroll
    for (int r = 0; r < 3; r++) {
        const float* a = &alphas[(r * 8 + h) * HDIM];
        float sq = 0.f, sk = 0.f;
        #pragma unroll
        for (int i = 0; i < HDIM; i++) { sq = fmaf(qh[i], a[i], sq); sk = fmaf(kh[i], a[i], sk); }
        ksm[(r * 8 + h) * 32 + nl] = ((ull)ford(sq) << 32) | (unsigned)n;
        ksm[(24 + r * 8 + h) * 32 + nl] = ((ull)ford(sk) << 32) | (unsigned)n;
    }

    #pragma unroll
    for (int i = 0; i < HDIM; i++) stage[h * 929 + nl * 29 + i] = qh[i];
    __syncthreads();
    for (int e = tid; e < 8 * 896; e += 256) {
        int hh = e / 896, rr = e - hh * 896;
        g_qhat[(size_t)hh * NTOK * 28 + (size_t)n0 * 28 + rr] =
            stage[hh * 929 + (rr / 28) * 29 + rr % 28];
    }
    __syncthreads();
    #pragma unroll
    for (int i = 0; i < HDIM; i++) stage[h * 929 + nl * 29 + i] = kh[i];
    __syncthreads();
    for (int e = tid; e < 8 * 896; e += 256) {
        int hh = e / 896, rr = e - hh * 896;
        g_khat[(size_t)hh * NTOK * 28 + (size_t)n0 * 28 + rr] =
            stage[hh * 929 + (rr / 28) * 29 + rr % 28];
    }
    for (int e = tid; e < 48 * 32; e += 256) {
        int seg = e >> 5, nn = e & 31;
        g_keys[(size_t)seg * NTOK + n0 + nn] = ksm[e];
    }
}

// ---------- bitonic: presort ----------
__global__ void __launch_bounds__(512) k_presort() {
    __shared__ __align__(16) ull s[CHUNK];
    int seg = blockIdx.x >> 3, chunk = blockIdx.x & 7;
    size_t gb = (size_t)seg * NTOK + (size_t)chunk * CHUNK;
    int base = chunk * CHUNK;
    int t = threadIdx.x;
    int e0 = t * 8;
    int g0 = base + e0;

    ull e[8];
    #pragma unroll
    for (int r = 0; r < 8; r++) e[r] = g_keys[gb + e0 + r];
    reg_tail<2>(e, g0);
    reg_tail<4>(e, g0);
    reg_tail<8>(e, g0);
    #pragma unroll
    for (int r = 0; r < 8; r++) s[e0 + r] = e[r];
    __syncthreads();

    for (int k = 16; k <= CHUNK; k <<= 1) {
        for (int j = k >> 1; j >= 8; j >>= 1) {
            int pbase = t * 4;
            int i = ((pbase & ~(j - 1)) << 1) | (pbase & (j - 1));
            bool asc = (((base + i) & k) == 0);
            spass4(s, pbase, j, asc);
            __syncthreads();
        }
        #pragma unroll
        for (int r = 0; r < 8; r++) e[r] = s[e0 + r];
        bool asc = ((g0 & k) == 0);
        tail8(e, asc);
        if (k < CHUNK) {
            #pragma unroll
            for (int r = 0; r < 8; r++) s[e0 + r] = e[r];
            __syncthreads();
        }
    }
    #pragma unroll
    for (int r = 0; r < 8; r++) g_keys[gb + e0 + r] = e[r];
}

// ---------- fused global merge ----------
__global__ void __launch_bounds__(256) k_gmerge(int k) {
    int t = blockIdx.x * 256 + threadIdx.x;
    int seg = t >> 12;
    int g = t & 4095;
    size_t bs = (size_t)seg * NTOK;
    ull e[8];
    #pragma unroll
    for (int m = 0; m < 8; m++) e[m] = g_keys[bs + g + 4096 * m];
    #pragma unroll
    for (int j = 4; j >= 1; j >>= 1) {
        if (j * 8192 <= k) {
            #pragma unroll
            for (int m = 0; m < 8; m++) {
                if (!(m & j)) {
                    bool asc = (((m * 4096) & k) == 0);
                    cswap(e[m], e[m + j], asc);
                }
            }
        }
    }
    #pragma unroll
    for (int m = 0; m < 8; m++) g_keys[bs + g + 4096 * m] = e[m];
}

// ---------- bitonic: finish ----------
__global__ void __launch_bounds__(512) k_finish(int k) {
    __shared__ __align__(16) ull s[CHUNK];
    int seg = blockIdx.x >> 3, chunk = blockIdx.x & 7;
    size_t gb = (size_t)seg * NTOK + (size_t)chunk * CHUNK;
    int base = chunk * CHUNK;
    int t = threadIdx.x;
    int e0 = t * 8;
    #pragma unroll
    for (int u = 0; u < 2; u++) {
        int i = (t + u * 512) * 4;
        *(ulonglong2*)(s + i)     = *(const ulonglong2*)(g_keys + gb + i);
        *(ulonglong2*)(s + i + 2) = *(const ulonglong2*)(g_keys + gb + i + 2);
    }
    __syncthreads();
    bool asc = ((base & k) == 0);
    for (int j = CHUNK >> 1; j >= 8; j >>= 1) {
        spass4(s, t * 4, j, asc);
        __syncthreads();
    }
    ull e[8];
    #pragma unroll
    for (int r = 0; r < 8; r++) e[r] = s[e0 + r];
    tail8(e, asc);
    #pragma unroll
    for (int r = 0; r < 8; r++) g_keys[gb + e0 + r] = e[r];
}

// ---------- block attention v3: 512 threads, 4x8 tiles (best measured) ----------
__global__ void __launch_bounds__(512) k_attn() {
    __shared__ __align__(16) float SP[11072];
    float* qs_t = SP;                          // [kk][row] 28 x 130
    float* ks   = SP + 3648;                   // [row][kk] 128 x 30
    float* vs   = SP + 7488;                   // [row][d]  128 x 26
    int* qidx = (int*)(SP + 10816);
    int* kidx = (int*)(SP + 10944);
    float* pbuf = SP;                          // [32 cols][rowpair], 32 x 134

    int tid = threadIdx.x;
    int b = blockIdx.x, h = blockIdx.y, r = blockIdx.z;
    int seg = r * 8 + h;

    if (tid < 128)
        qidx[tid] = (int)(g_keys[(size_t)seg * NTOK + b * 128 + tid] & 0xffffffffu);
    else if (tid < 256) {
        int t = tid - 128;
        kidx[t] = (int)(g_keys[(size_t)(24 + seg) * NTOK + b * 128 + t] & 0xffffffffu);
    }
    __syncthreads();
    for (int i = tid; i < 128 * 28; i += 512) {
        int row = i / 28, kk = i - row * 28;
        qs_t[kk * 130 + row] = g_qhat[((size_t)h * NTOK + qidx[row]) * HDIM + kk];
        ks[row * 30 + kk]    = g_khat[((size_t)h * NTOK + kidx[row]) * HDIM + kk];
    }
    for (int i = tid; i < 128 * 24; i += 512) {
        int row = i / 24, kk = i - row * 24;
        vs[row * 26 + kk] = g_qkv[(size_t)kidx[row] * 576 + 384 + h * 24 + kk];
    }
    __syncthreads();

    int ty = tid >> 4, tx = tid & 15;          // ty 0..31
    int R0 = ty * 4;                           // rows R0..R0+3
    ull acc2[2][8];                            // [rowpair u][col c]: rows (R0+2u, R0+2u+1)
    #pragma unroll
    for (int u = 0; u < 2; u++)
        #pragma unroll
        for (int c = 0; c < 8; c++) acc2[u][c] = 0ULL;

    #pragma unroll 2
    for (int kk = 0; kk < 28; kk++) {
        ull qp0 = *(const ull*)&qs_t[kk * 130 + R0];
        ull qp1 = *(const ull*)&qs_t[kk * 130 + R0 + 2];
        #pragma unroll
        for (int c = 0; c < 8; c++) {
            float kv = ks[(tx + 16 * c) * 30 + kk];
            unsigned kb = __float_as_uint(kv);
            ull kp;
            PACK_F32X2(kp, kb, kb);
            FMA_F32X2(acc2[0][c], qp0, kp, acc2[0][c]);
            FMA_F32X2(acc2[1][c], qp1, kp, acc2[1][c]);
        }
    }

    // softmax per rowpair (transient unpack; keeps regs low)
    #pragma unroll
    for (int u = 0; u < 2; u++) {
        float vlo[8], vhi[8];
        #pragma unroll
        for (int c = 0; c < 8; c++) {
            unsigned lo, hi;
            UNPACK_F32X2(lo, hi, acc2[u][c]);
            vlo[c] = __uint_as_float(lo);
            vhi[c] = __uint_as_float(hi);
        }
        float mlo = vlo[0], mhi = vhi[0];
        #pragma unroll
        for (int c = 1; c < 8; c++) { mlo = fmaxf(mlo, vlo[c]); mhi = fmaxf(mhi, vhi[c]); }
        #pragma unroll
        for (int s = 1; s < 16; s <<= 1) {
            mlo = fmaxf(mlo, __shfl_xor_sync(0xffffffffu, mlo, s));
            mhi = fmaxf(mhi, __shfl_xor_sync(0xffffffffu, mhi, s));
        }
        float slo = 0.f, shi = 0.f;
        #pragma unroll
        for (int c = 0; c < 8; c++) {
            vlo[c] = __expf(vlo[c] - mlo); slo += vlo[c];
            vhi[c] = __expf(vhi[c] - mhi); shi += vhi[c];
        }
        #pragma unroll
        for (int s = 1; s < 16; s <<= 1) {
            slo += __shfl_xor_sync(0xffffffffu, slo, s);
            shi += __shfl_xor_sync(0xffffffffu, shi, s);
        }
        float ilo = 1.f / slo, ihi = 1.f / shi;
        #pragma unroll
        for (int c = 0; c < 8; c++) {
            unsigned lo = __float_as_uint(vlo[c] * ilo);
            unsigned hi = __float_as_uint(vhi[c] * ihi);
            PACK_F32X2(acc2[u][c], lo, hi);
        }
        if (tx == 0) {
            g_z[(size_t)seg * NTOK + qidx[R0 + 2 * u]]     = __logf(slo) + mlo;
            g_z[(size_t)seg * NTOK + qidx[R0 + 2 * u + 1]] = __logf(shi) + mhi;
        }
    }

    // PV: 4 rounds of 32 cols; thread = (rowpair s, dim-group dg of 3)
    int s = tid & 63;                  // rowpair: rows 2s, 2s+1
    int dg = tid >> 6;                 // 0..7 → dims dg*3 .. dg*3+2
    ull oap[3];
    #pragma unroll
    for (int d = 0; d < 3; d++) oap[d] = 0ULL;

    for (int round = 0; round < 4; round++) {
        __syncthreads();
        #pragma unroll
        for (int cc2 = 0; cc2 < 2; cc2++) {
            int cc = round * 2 + cc2;
            int lc = tx + 16 * cc2;
            *(ull*)&pbuf[lc * 134 + R0]     = acc2[0][cc];
            *(ull*)&pbuf[lc * 134 + R0 + 2] = acc2[1][cc];
        }
        __syncthreads();
        #pragma unroll 4
        for (int c16 = 0; c16 < 32; c16++) {
            ull pp = *(const ull*)&pbuf[c16 * 134 + 2 * s];
            int gcol = round * 32 + c16;
            const float* vv = &vs[gcol * 26 + dg * 3];
            #pragma unroll
            for (int d = 0; d < 3; d++) {
                unsigned vb = __float_as_uint(vv[d]);
                ull vp;
                PACK_F32X2(vp, vb, vb);
                FMA_F32X2(oap[d], pp, vp, oap[d]);
            }
        }
    }
    {
        int n0 = qidx[2 * s], n1 = qidx[2 * s + 1];
        float* o0 = &g_o[((size_t)seg * NTOK + n0) * 24 + dg * 3];
        float* o1 = &g_o[((size_t)seg * NTOK + n1) * 24 + dg * 3];
        #pragma unroll
        for (int d = 0; d < 3; d++) {
            unsigned lo, hi;
            UNPACK_F32X2(lo, hi, oap[d]);
            o0[d] = __uint_as_float(lo);
            o1[d] = __uint_as_float(hi);
        }
    }
}

// ---------- combine ----------
__global__ void __launch_bounds__(512) k_combine(
    const float* __restrict__ x, const float* __restrict__ Wo, const float* __restrict__ bo,
    const float* __restrict__ g2, const float* __restrict__ b2v,
    const float* __restrict__ W1, const float* __restrict__ b1v,
    const float* __restrict__ W2, const float* __restrict__ b2f,
    float* __restrict__ out) {
    __shared__ float Wo_s[4608];
    __shared__ float outs[16][192];
    __shared__ float wsm[16][24];
    __shared__ float hsm[16][24];
    __shared__ float fsm[16][24];
    int warp = threadIdx.x >> 5, lane = threadIdx.x & 31;
    int row = blockIdx.x * 16 + warp;

    for (int i = threadIdx.x; i < 4608; i += 512) Wo_s[i] = Wo[i];
    __syncthreads();

    if (lane < 8) {
        int h = lane;
        float z0 = g_z[(size_t)h * NTOK + row];
        float z1 = g_z[(size_t)(8 + h) * NTOK + row];
        float z2 = g_z[(size_t)(16 + h) * NTOK + row];
        float m = fmaxf(z0, fmaxf(z1, z2));
        float e0 = __expf(z0 - m), e1 = __expf(z1 - m), e2 = __expf(z2 - m);
        float inv = 1.f / (e0 + e1 + e2);
        wsm[warp][h * 3 + 0] = e0 * inv;
        wsm[warp][h * 3 + 1] = e1 * inv;
        wsm[warp][h * 3 + 2] = e2 * inv;
    }
    __syncwarp();
    #pragma unroll
    for (int u = 0; u < 6; u++) {
        int j = lane * 6 + u;
        int h = j / 24, d = j - h * 24;
        float a = 0.f;
        #pragma unroll
        for (int r = 0; r < 3; r++)
            a = fmaf(wsm[warp][h * 3 + r], g_o[((size_t)(r * 8 + h) * NTOK + row) * 24 + d], a);
        outs[warp][j] = a;
    }
    __syncwarp();
    float xv = 0.f;
    if (lane < 24) {
        float a = bo[lane];
        #pragma unroll 4
        for (int j = 0; j < 192; j++) a = fmaf(outs[warp][j], Wo_s[j * 24 + lane], a);
        xv = x[(size_t)row * 24 + lane] + a;
    }
    float s = (lane < 24) ? xv : 0.f;
    #pragma unroll
    for (int t = 16; t > 0; t >>= 1) s += __shfl_xor_sync(0xffffffffu, s, t);
    float mu = s * (1.f / 24.f);
    float dv = (lane < 24) ? (xv - mu) : 0.f;
    float v2 = dv * dv;
    #pragma unroll
    for (int t = 16; t > 0; t >>= 1) v2 += __shfl_xor_sync(0xffffffffu, v2, t);
    float inv = rsqrtf(v2 * (1.f / 24.f) + 1e-5f);
    if (lane < 24) hsm[warp][lane] = dv * inv * g2[lane] + b2v[lane];
    __syncwarp();
    if (lane < 24) {
        float f = b1v[lane];
        #pragma unroll
        for (int j = 0; j < 24; j++) f = fmaf(hsm[warp][j], W1[j * 24 + lane], f);
        fsm[warp][lane] = fmaxf(f, 0.f);
    }
    __syncwarp();
    if (lane < 24) {
        float f = b2f[lane];
        #pragma unroll
        for (int j = 0; j < 24; j++) f = fmaf(fsm[warp][j], W2[j * 24 + lane], f);
        out[(size_t)row * 24 + lane] = xv + f;
    }
}

extern "C" void kernel_launch(void* const* d_in, const int* in_sizes, int n_in,
                              void* d_out, int out_size) {
    const float* x      = (const float*)d_in[0];
    const float* coords = (const float*)d_in[1];
    const float* n1g    = (const float*)d_in[2];
    const float* n1b    = (const float*)d_in[3];
    const float* Wq     = (const float*)d_in[4];
    const float* Wk     = (const float*)d_in[5];
    const float* Wv     = (const float*)d_in[6];
    const float* wrpe   = (const float*)d_in[7];
    const float* Wo     = (const float*)d_in[8];
    const float* bo     = (const float*)d_in[9];
    const float* n2g    = (const float*)d_in[10];
    const float* n2b    = (const float*)d_in[11];
    const float* W1     = (const float*)d_in[12];
    const float* b1     = (const float*)d_in[13];
    const float* W2     = (const float*)d_in[14];
    const float* b2     = (const float*)d_in[15];
    const float* alphas = (const float*)d_in[16];
    float* out = (float*)d_out;

    k_ln_qkv<<<NTOK / 64, 576>>>(x, n1g, n1b, Wq, Wk, Wv);
    k_build<<<NTOK / 32, 256>>>(coords, alphas, wrpe);

    k_presort<<<NSEG * 8, 512>>>();
    k_gmerge<<<768, 256>>>(8192);
    k_finish<<<NSEG * 8, 512>>>(8192);
    k_gmerge<<<768, 256>>>(16384);
    k_finish<<<NSEG * 8, 512>>>(16384);
    k_gmerge<<<768, 256>>>(32768);
    k_finish<<<NSEG * 8, 512>>>(32768);

    dim3 ag(NTOK / 128, NH, 3);
    k_attn<<<ag, 512>>>();
    k_combine<<<NTOK / 16, 512>>>(x, Wo, bo, n2g, n2b, W1, b1, W2, b2, out);
}